// round 1
// baseline (speedup 1.0000x reference)
#include <cuda_runtime.h>

#define N3 262144
#define N2 65536
#define N1 16384

// ---------------- scratch (device globals; no allocations allowed) ----------
__device__ float g_x8   [N3 * 16];  // enc1 out
__device__ float g_x7p  [N2 * 16];  // pooled
__device__ float g_x7   [N2 * 32];  // enc2 out
__device__ float g_x6p  [N1 * 32];  // pooled
__device__ float g_x6   [N1 * 64];  // enc3 out
__device__ float g_x7dec[N2 * 32];  // dec1 out
__device__ float g_x8dec[N3 * 16];  // dec2 out
__device__ int   g_pidx3[N3];
__device__ int   g_pidx2[N2];

// ---------------- helpers ----------------------------------------------------
__global__ void zero_kernel(float* p, int n) {
    int i = blockIdx.x * blockDim.x + threadIdx.x;
    int stride = gridDim.x * blockDim.x;
    for (; i < n; i += stride) p[i] = 0.0f;
}

// pidx[i] = searchsorted(keys_par, keys_child[i] >> 2)   (side='left')
__global__ void pidx_kernel(const int* __restrict__ keys_child,
                            const int* __restrict__ keys_par,
                            int Nc, int Np, int* __restrict__ pidx) {
    int i = blockIdx.x * blockDim.x + threadIdx.x;
    if (i >= Nc) return;
    int v = keys_child[i] >> 2;
    int lo = 0, hi = Np;
    while (lo < hi) {
        int mid = (lo + hi) >> 1;
        if (keys_par[mid] < v) lo = mid + 1; else hi = mid;
    }
    pidx[i] = lo;
}

// segment-max pool. Values are post-ReLU (>= 0) so int-bit atomicMax == float max,
// and 0-init matches the reference's (-inf -> 0) fill.
template <int C>
__global__ void pool_kernel(const float* __restrict__ child,
                            const int* __restrict__ pidx,
                            int Nc, int Np, float* __restrict__ parent) {
    int i = blockIdx.x * blockDim.x + threadIdx.x;
    if (i >= Nc * C) return;
    int node = i / C;
    int c = i - node * C;
    int p = pidx[node];
    if (p < Np) {
        float v = child[i];
        atomicMax(reinterpret_cast<int*>(&parent[(size_t)p * C + c]),
                  __float_as_int(v));
    }
}

// ---------------- fused gather + (9*CIN -> COUT) matmul ----------------------
// Thread-per-node. Per-neighbor weight slab staged in shared as [COUT][CIN]
// (row-contiguous) so the inner loop is uniform-address LDS.128 broadcast:
// 1 LDS per 4 FFMA. INDIRECT fuses the unpool: feat row = clamp(pidx[idx]).
template <int CIN, int COUT, bool RELU, bool INDIRECT>
__global__ void __launch_bounds__(128)
conv_kernel(const float* __restrict__ feat, const int* __restrict__ neigh,
            const int* __restrict__ pidx, int Nfeat, int N,
            const float* __restrict__ w, const float* __restrict__ b,
            float* __restrict__ out) {
    __shared__ float ws[CIN * COUT];
    const int n = blockIdx.x * blockDim.x + threadIdx.x;

    float acc[COUT];
#pragma unroll
    for (int o = 0; o < COUT; o++) acc[o] = b[o];

    int idx[9];
    if (n < N) {
#pragma unroll
        for (int j = 0; j < 9; j++) idx[j] = neigh[n * 9 + j];
    } else {
#pragma unroll
        for (int j = 0; j < 9; j++) idx[j] = -1;
    }
    if (INDIRECT) {
#pragma unroll
        for (int j = 0; j < 9; j++) {
            if (idx[j] >= 0) {
                int p = pidx[idx[j]];
                idx[j] = p < Nfeat ? p : Nfeat - 1;  // jax gather clamp
            }
        }
    }

    for (int j = 0; j < 9; j++) {
        __syncthreads();
        // stage weight slab for neighbor j: ws[o*CIN + c] = w[o, j*CIN + c]
        for (int t = threadIdx.x; t < CIN * COUT; t += blockDim.x) {
            int o = t / CIN, c = t - o * CIN;
            ws[t] = w[o * (9 * CIN) + j * CIN + c];
        }
        __syncthreads();
        const int id = idx[j];
        if (id < 0) continue;
        const float* fr = feat + (size_t)id * CIN;
        if constexpr (CIN % 4 == 0) {
#pragma unroll
            for (int c4 = 0; c4 < CIN; c4 += 4) {
                float4 f = *reinterpret_cast<const float4*>(fr + c4);
#pragma unroll
                for (int o = 0; o < COUT; o++) {
                    float4 wv = *reinterpret_cast<const float4*>(&ws[o * CIN + c4]);
                    acc[o] += f.x * wv.x + f.y * wv.y + f.z * wv.z + f.w * wv.w;
                }
            }
        } else {
#pragma unroll
            for (int c = 0; c < CIN; c++) {
                float f = fr[c];
#pragma unroll
                for (int o = 0; o < COUT; o++) acc[o] += f * ws[o * CIN + c];
            }
        }
    }

    if (n < N) {
        if constexpr (COUT % 4 == 0) {
#pragma unroll
            for (int o = 0; o < COUT; o += 4) {
                float4 v;
                v.x = RELU ? fmaxf(acc[o + 0], 0.f) : acc[o + 0];
                v.y = RELU ? fmaxf(acc[o + 1], 0.f) : acc[o + 1];
                v.z = RELU ? fmaxf(acc[o + 2], 0.f) : acc[o + 2];
                v.w = RELU ? fmaxf(acc[o + 3], 0.f) : acc[o + 3];
                *reinterpret_cast<float4*>(&out[(size_t)n * COUT + o]) = v;
            }
        } else {
#pragma unroll
            for (int o = 0; o < COUT; o++)
                out[(size_t)n * COUT + o] = RELU ? fmaxf(acc[o], 0.f) : acc[o];
        }
    }
}

// ---------------- launch ------------------------------------------------------
static inline int cdiv(int a, int b) { return (a + b - 1) / b; }

extern "C" void kernel_launch(void* const* d_in, const int* in_sizes, int n_in,
                              void* d_out, int out_size) {
    const float* features = (const float*)d_in[0];
    const int* keys3   = (const int*)d_in[1];
    const int* keys2   = (const int*)d_in[2];
    const int* keys1   = (const int*)d_in[3];
    const int* neighs3 = (const int*)d_in[4];
    const int* neighs2 = (const int*)d_in[5];
    const int* neighs1 = (const int*)d_in[6];
    const float* w_enc1 = (const float*)d_in[7];
    const float* b_enc1 = (const float*)d_in[8];
    const float* w_enc2 = (const float*)d_in[9];
    const float* b_enc2 = (const float*)d_in[10];
    const float* w_enc3 = (const float*)d_in[11];
    const float* b_enc3 = (const float*)d_in[12];
    const float* w_dec1 = (const float*)d_in[13];
    const float* b_dec1 = (const float*)d_in[14];
    const float* w_dec2 = (const float*)d_in[15];
    const float* b_dec2 = (const float*)d_in[16];
    const float* w_head = (const float*)d_in[17];
    const float* b_head = (const float*)d_in[18];
    float* out = (float*)d_out;

    float *x8, *x7p, *x7, *x6p, *x6, *x7dec, *x8dec;
    int *pidx3, *pidx2;
    cudaGetSymbolAddress((void**)&x8, g_x8);
    cudaGetSymbolAddress((void**)&x7p, g_x7p);
    cudaGetSymbolAddress((void**)&x7, g_x7);
    cudaGetSymbolAddress((void**)&x6p, g_x6p);
    cudaGetSymbolAddress((void**)&x6, g_x6);
    cudaGetSymbolAddress((void**)&x7dec, g_x7dec);
    cudaGetSymbolAddress((void**)&x8dec, g_x8dec);
    cudaGetSymbolAddress((void**)&pidx3, g_pidx3);
    cudaGetSymbolAddress((void**)&pidx2, g_pidx2);

    // parent-index precompute (shared by pool + fused unpool)
    pidx_kernel<<<cdiv(N3, 256), 256>>>(keys3, keys2, N3, N2, pidx3);
    pidx_kernel<<<cdiv(N2, 256), 256>>>(keys2, keys1, N2, N1, pidx2);

    // zero pool accumulators (must be re-zeroed every call: atomicMax)
    zero_kernel<<<256, 256>>>(x7p, N2 * 16);
    zero_kernel<<<256, 256>>>(x6p, N1 * 32);

    // enc1: [N3,1] -> [N3,16]
    conv_kernel<1, 16, true, false><<<cdiv(N3, 128), 128>>>(
        features, neighs3, nullptr, N3, N3, w_enc1, b_enc1, x8);
    // pool 3->2
    pool_kernel<16><<<cdiv(N3 * 16, 256), 256>>>(x8, pidx3, N3, N2, x7p);
    // enc2: [N2,16] -> [N2,32]
    conv_kernel<16, 32, true, false><<<cdiv(N2, 128), 128>>>(
        x7p, neighs2, nullptr, N2, N2, w_enc2, b_enc2, x7);
    // pool 2->1
    pool_kernel<32><<<cdiv(N2 * 32, 256), 256>>>(x7, pidx2, N2, N1, x6p);
    // enc3: [N1,32] -> [N1,64]
    conv_kernel<32, 64, true, false><<<cdiv(N1, 128), 128>>>(
        x6p, neighs1, nullptr, N1, N1, w_enc3, b_enc3, x6);
    // dec1 (unpool 1->2 fused via pidx2): gather x6[pidx2[idx]] -> [N2,32]
    conv_kernel<64, 32, true, true><<<cdiv(N2, 128), 128>>>(
        x6, neighs2, pidx2, N1, N2, w_dec1, b_dec1, x7dec);
    // dec2 (unpool 2->3 fused via pidx3): gather x7dec[pidx3[idx]] -> [N3,16]
    conv_kernel<32, 16, true, true><<<cdiv(N3, 128), 128>>>(
        x7dec, neighs3, pidx3, N2, N3, w_dec2, b_dec2, x8dec);
    // head: [N3,16] -> [N3,1], no relu
    conv_kernel<16, 1, false, false><<<cdiv(N3, 128), 128>>>(
        x8dec, neighs3, nullptr, N3, N3, w_head, b_head, out);
}

// round 2
// speedup vs baseline: 1.0933x; 1.0933x over previous
#include <cuda_runtime.h>

#define N3 262144
#define N2 65536
#define N1 16384

// ---------------- scratch (device globals; no allocations allowed) ----------
__device__ float g_x8   [N3 * 16];
__device__ float g_x7p  [N2 * 16];
__device__ float g_x7   [N2 * 32];
__device__ float g_x6p  [N1 * 32];
__device__ float g_x6   [N1 * 64];
__device__ float g_x7dec[N2 * 32];
__device__ float g_x8dec[N3 * 16];
__device__ int   g_pidx3[N3];
__device__ int   g_pidx2[N2];

// ---------------- helpers ----------------------------------------------------
__global__ void zero_kernel(float* p, int n) {
    int i = blockIdx.x * blockDim.x + threadIdx.x;
    int stride = gridDim.x * blockDim.x;
    for (; i < n; i += stride) p[i] = 0.0f;
}

// pidx[i] = searchsorted(keys_par, keys_child[i] >> 2)   (side='left')
__global__ void pidx_kernel(const int* __restrict__ keys_child,
                            const int* __restrict__ keys_par,
                            int Nc, int Np, int* __restrict__ pidx) {
    int i = blockIdx.x * blockDim.x + threadIdx.x;
    if (i >= Nc) return;
    int v = keys_child[i] >> 2;
    int lo = 0, hi = Np;
    while (lo < hi) {
        int mid = (lo + hi) >> 1;
        if (keys_par[mid] < v) lo = mid + 1; else hi = mid;
    }
    pidx[i] = lo;
}

// segment-max pool. Post-ReLU values >= 0, so int-bit atomicMax == float max
// and 0-init matches the reference's (-inf -> 0) fill.
template <int C>
__global__ void pool_kernel(const float* __restrict__ child,
                            const int* __restrict__ pidx,
                            int Nc, int Np, float* __restrict__ parent) {
    int i = blockIdx.x * blockDim.x + threadIdx.x;
    if (i >= Nc * C) return;
    int node = i / C;
    int c = i - node * C;
    int p = pidx[node];
    if (p < Np) {
        float v = child[i];
        atomicMax(reinterpret_cast<int*>(&parent[(size_t)p * C + c]),
                  __float_as_int(v));
    }
}

// ---------------- fused gather + (9*CIN -> COB) matmul -----------------------
// Whole weight slab for this block's COB output columns staged ONCE in shared
// ([j][o][c] layout, <=48KB by construction). NPN nodes per thread amortize
// the LDS.128 broadcast and double gather MLP. No syncs inside the j loop.
// INDIRECT fuses the unpool gather (feat row = clamp(pidx[idx])).
template <int CIN, int COB, int NPN, bool RELU, bool INDIRECT>
__global__ void __launch_bounds__(128)
conv_kernel(const float* __restrict__ feat, const int* __restrict__ neigh,
            const int* __restrict__ pidx, int Nfeat, int N, int ostride,
            const float* __restrict__ w, const float* __restrict__ b,
            float* __restrict__ out) {
    __shared__ float ws[9 * CIN * COB];
    const int tid = threadIdx.x;
    const int oc_base = blockIdx.y * COB;
    const int cin9 = 9 * CIN;

    // stage full slab: ws[(j*COB + o)*CIN + c] = w[oc_base+o][j*CIN + c]
    for (int s = tid; s < COB * cin9; s += 128) {
        int o = s / cin9;
        int rem = s - o * cin9;      // = j*CIN + c
        int j = rem / CIN;
        int c = rem - j * CIN;
        ws[(j * COB + o) * CIN + c] = w[(size_t)(oc_base + o) * cin9 + rem];
    }
    __syncthreads();

    int node[NPN];
    int idx[NPN][9];
#pragma unroll
    for (int t = 0; t < NPN; t++) {
        node[t] = blockIdx.x * (128 * NPN) + t * 128 + tid;
#pragma unroll
        for (int j = 0; j < 9; j++) idx[t][j] = neigh[(size_t)node[t] * 9 + j];
        if (INDIRECT) {
#pragma unroll
            for (int j = 0; j < 9; j++) {
                if (idx[t][j] >= 0) {
                    int p = pidx[idx[t][j]];
                    idx[t][j] = p < Nfeat ? p : Nfeat - 1;
                }
            }
        }
    }

    float acc[NPN][COB];
#pragma unroll
    for (int t = 0; t < NPN; t++)
#pragma unroll
        for (int o = 0; o < COB; o++) acc[t][o] = b[oc_base + o];

    if constexpr (CIN == 1) {
#pragma unroll
        for (int j = 0; j < 9; j++) {
            float f[NPN];
#pragma unroll
            for (int t = 0; t < NPN; t++)
                f[t] = (idx[t][j] >= 0) ? __ldg(&feat[idx[t][j]]) : 0.0f;
#pragma unroll
            for (int o = 0; o < COB; o++) {
                float wv = ws[j * COB + o];
#pragma unroll
                for (int t = 0; t < NPN; t++) acc[t][o] += f[t] * wv;
            }
        }
    } else {
        for (int j = 0; j < 9; j++) {
#pragma unroll 2
            for (int c4 = 0; c4 < CIN; c4 += 4) {
                float4 f[NPN];
#pragma unroll
                for (int t = 0; t < NPN; t++) {
                    if (idx[t][j] >= 0)
                        f[t] = *reinterpret_cast<const float4*>(
                            &feat[(size_t)idx[t][j] * CIN + c4]);
                    else
                        f[t] = make_float4(0.f, 0.f, 0.f, 0.f);
                }
#pragma unroll
                for (int o = 0; o < COB; o++) {
                    float4 wv = *reinterpret_cast<const float4*>(
                        &ws[(j * COB + o) * CIN + c4]);
#pragma unroll
                    for (int t = 0; t < NPN; t++) {
                        acc[t][o] += f[t].x * wv.x + f[t].y * wv.y +
                                     f[t].z * wv.z + f[t].w * wv.w;
                    }
                }
            }
        }
    }

#pragma unroll
    for (int t = 0; t < NPN; t++) {
        float* orow = out + (size_t)node[t] * ostride + oc_base;
        if constexpr (COB % 4 == 0) {
#pragma unroll
            for (int o = 0; o < COB; o += 4) {
                float4 v;
                v.x = RELU ? fmaxf(acc[t][o + 0], 0.f) : acc[t][o + 0];
                v.y = RELU ? fmaxf(acc[t][o + 1], 0.f) : acc[t][o + 1];
                v.z = RELU ? fmaxf(acc[t][o + 2], 0.f) : acc[t][o + 2];
                v.w = RELU ? fmaxf(acc[t][o + 3], 0.f) : acc[t][o + 3];
                *reinterpret_cast<float4*>(orow + o) = v;
            }
        } else {
#pragma unroll
            for (int o = 0; o < COB; o++)
                orow[o] = RELU ? fmaxf(acc[t][o], 0.f) : acc[t][o];
        }
    }
}

// ---------------- launch ------------------------------------------------------
static inline int cdiv(int a, int b) { return (a + b - 1) / b; }

extern "C" void kernel_launch(void* const* d_in, const int* in_sizes, int n_in,
                              void* d_out, int out_size) {
    const float* features = (const float*)d_in[0];
    const int* keys3   = (const int*)d_in[1];
    const int* keys2   = (const int*)d_in[2];
    const int* keys1   = (const int*)d_in[3];
    const int* neighs3 = (const int*)d_in[4];
    const int* neighs2 = (const int*)d_in[5];
    const int* neighs1 = (const int*)d_in[6];
    const float* w_enc1 = (const float*)d_in[7];
    const float* b_enc1 = (const float*)d_in[8];
    const float* w_enc2 = (const float*)d_in[9];
    const float* b_enc2 = (const float*)d_in[10];
    const float* w_enc3 = (const float*)d_in[11];
    const float* b_enc3 = (const float*)d_in[12];
    const float* w_dec1 = (const float*)d_in[13];
    const float* b_dec1 = (const float*)d_in[14];
    const float* w_dec2 = (const float*)d_in[15];
    const float* b_dec2 = (const float*)d_in[16];
    const float* w_head = (const float*)d_in[17];
    const float* b_head = (const float*)d_in[18];
    float* out = (float*)d_out;

    float *x8, *x7p, *x7, *x6p, *x6, *x7dec, *x8dec;
    int *pidx3, *pidx2;
    cudaGetSymbolAddress((void**)&x8, g_x8);
    cudaGetSymbolAddress((void**)&x7p, g_x7p);
    cudaGetSymbolAddress((void**)&x7, g_x7);
    cudaGetSymbolAddress((void**)&x6p, g_x6p);
    cudaGetSymbolAddress((void**)&x6, g_x6);
    cudaGetSymbolAddress((void**)&x7dec, g_x7dec);
    cudaGetSymbolAddress((void**)&x8dec, g_x8dec);
    cudaGetSymbolAddress((void**)&pidx3, g_pidx3);
    cudaGetSymbolAddress((void**)&pidx2, g_pidx2);

    // parent-index precompute (shared by pool + fused unpool)
    pidx_kernel<<<cdiv(N3, 256), 256>>>(keys3, keys2, N3, N2, pidx3);
    pidx_kernel<<<cdiv(N2, 256), 256>>>(keys2, keys1, N2, N1, pidx2);

    // zero pool accumulators (atomicMax needs fresh zeros every call)
    zero_kernel<<<256, 256>>>(x7p, N2 * 16);
    zero_kernel<<<256, 256>>>(x6p, N1 * 32);

    // enc1: [N3,1] -> [N3,16]   (gather-bound; NPN=4)
    conv_kernel<1, 16, 4, true, false><<<dim3(N3 / (128 * 4), 1), 128>>>(
        features, neighs3, nullptr, N3, N3, 16, w_enc1, b_enc1, x8);
    // pool 3->2
    pool_kernel<16><<<cdiv(N3 * 16, 256), 256>>>(x8, pidx3, N3, N2, x7p);
    // enc2: [N2,16] -> [N2,32]
    conv_kernel<16, 32, 2, true, false><<<dim3(N2 / (128 * 2), 1), 128>>>(
        x7p, neighs2, nullptr, N2, N2, 32, w_enc2, b_enc2, x7);
    // pool 2->1
    pool_kernel<32><<<cdiv(N2 * 32, 256), 256>>>(x7, pidx2, N2, N1, x6p);
    // enc3: [N1,32] -> [N1,64]   (COUT split x2 for occupancy)
    conv_kernel<32, 32, 1, true, false><<<dim3(N1 / 128, 2), 128>>>(
        x6p, neighs1, nullptr, N1, N1, 64, w_enc3, b_enc3, x6);
    // dec1 (unpool 1->2 fused): [N2, 9*64] -> [N2,32]  (COUT split x2)
    conv_kernel<64, 16, 2, true, true><<<dim3(N2 / (128 * 2), 2), 128>>>(
        x6, neighs2, pidx2, N1, N2, 32, w_dec1, b_dec1, x7dec);
    // dec2 (unpool 2->3 fused): [N3, 9*32] -> [N3,16]
    conv_kernel<32, 16, 2, true, true><<<dim3(N3 / (128 * 2), 1), 128>>>(
        x7dec, neighs3, pidx3, N2, N3, 16, w_dec2, b_dec2, x8dec);
    // head: [N3,16] -> [N3,1], no relu
    conv_kernel<16, 1, 4, false, false><<<dim3(N3 / (128 * 4), 1), 128>>>(
        x8dec, neighs3, nullptr, N3, N3, 1, w_head, b_head, out);
}